// round 6
// baseline (speedup 1.0000x reference)
#include <cuda_runtime.h>
#include <cstdint>

#define N_NODES 100000
#define DFEAT   64
#define NCOEF   8
#define KTOT    576
#define NGRAPHS 512
#define NTARG   10
#define NEDGES  1200000

#define NTILE     128          // nodes per CTA
#define TPB       256
#define KCHUNKS   9
#define SW2_STRIDE 132         // floats per weight row: 64k x 2(dup) + 4 pad
#define SFP_STRIDE 132         // floats per pair row:   64k x 2(pair) + 4 pad
#define KAN_SMEM  ((64 * SW2_STRIDE + 64 * SFP_STRIDE) * 4)   // 67584 B

// ---------------- static device scratch -------------------------------------
__device__ __align__(128) float g_y [N_NODES * DFEAT];
__device__ __align__(128) float g_h [N_NODES * DFEAT];
__device__ __align__(128) float g_y2[N_NODES * DFEAT];
__device__ __align__(128) float g_pool[NGRAPHS * DFEAT];
__device__ __align__(128) float g_Wh[NTARG * KTOT];
// duplicated, row-permuted weights: [layer][chunk][64 phys rows x 128 floats]
__device__ __align__(128) float g_W2[2][KCHUNKS][64 * 128];

// ---------------- math helpers ----------------------------------------------
__device__ __forceinline__ float silu_f(float v) { return v / (1.0f + __expf(-v)); }

// cardinal cubic B-spline, support (0,4): basis g value at p is n3(p - g)
// grid t_j = (j-3)*0.4 - 1  ->  p = (x + 2.2) * 2.5
__device__ __forceinline__ float n3(float t) {
    float r = 0.0f;
    if (t > 0.0f && t < 4.0f) {
        if (t < 1.0f)      { r = t * t * t * (1.0f / 6.0f); }
        else if (t < 2.0f) { float u = t - 1.0f; r = (1.0f + 3.0f*u + 3.0f*u*u - 3.0f*u*u*u) * (1.0f/6.0f); }
        else if (t < 3.0f) { float u = t - 2.0f; r = (4.0f - 6.0f*u*u + 3.0f*u*u*u) * (1.0f/6.0f); }
        else               { float u = 4.0f - t; r = u * u * u * (1.0f/6.0f); }
    }
    return r;
}

// packed f32x2 FMA: acc = a*b + acc (component-wise, full fp32 per lane)
#define FMA2(acc, a, b) \
    asm("fma.rn.f32x2 %0, %1, %2, %0;" : "+l"(acc) : "l"(a), "l"(b))

// ---------------- weight prep: duplicated + permuted W_eff ------------------
__global__ void k_prep(const float* __restrict__ bw0, const float* __restrict__ sw0, const float* __restrict__ sc0,
                       const float* __restrict__ bw1, const float* __restrict__ sw1, const float* __restrict__ sc1,
                       const float* __restrict__ bwh, const float* __restrict__ swh, const float* __restrict__ sch) {
    int idx = blockIdx.x * blockDim.x + threadIdx.x;
    if (idx >= DFEAT * KTOT) return;
    int o = idx / KTOT, k = idx % KTOT;
    float v0, v1;
    if (k < DFEAT) {
        v0 = bw0[o * DFEAT + k];
        v1 = bw1[o * DFEAT + k];
    } else {
        int k2 = k - DFEAT;
        int i = k2 >> 3, g = k2 & 7;
        v0 = sw0[(o * DFEAT + i) * NCOEF + g] * sc0[o * DFEAT + i];
        v1 = sw1[(o * DFEAT + i) * NCOEF + g] * sc1[o * DFEAT + i];
    }
    int chunk = k >> 6, kk = k & 63;
    int phys = ((o & 7) << 3) | (o >> 3);          // row permutation for bank spread
    int base = phys * 128 + kk * 2;
    g_W2[0][chunk][base]     = v0;
    g_W2[0][chunk][base + 1] = v0;
    g_W2[1][chunk][base]     = v1;
    g_W2[1][chunk][base + 1] = v1;
    if (o < NTARG) {
        float vh;
        if (k < DFEAT) {
            vh = bwh[o * DFEAT + k];
        } else {
            int k2 = k - DFEAT;
            int i = k2 >> 3, g = k2 & 7;
            vh = swh[(o * DFEAT + i) * NCOEF + g] * sch[o * DFEAT + i];
        }
        g_Wh[o * KTOT + k] = vh;
    }
}

// ---------------- utility kernels -------------------------------------------
__global__ void k_copy4(float4* __restrict__ dst, const float4* __restrict__ src, int n4) {
    int i = blockIdx.x * blockDim.x + threadIdx.x;
    if (i < n4) dst[i] = src[i];
}
__global__ void k_zero(float* __restrict__ dst, int n) {
    int i = blockIdx.x * blockDim.x + threadIdx.x;
    if (i < n) dst[i] = 0.0f;
}

// ---------------- edge scatter: dstbuf[dst] += feat[src] --------------------
__global__ void k_scatter(const float* __restrict__ feat, float* __restrict__ dstbuf,
                          const int* __restrict__ ei) {
    int idx = blockIdx.x * blockDim.x + threadIdx.x;
    if (idx >= NEDGES * 16) return;
    int e = idx >> 4;
    int c = idx & 15;
    int s = __ldg(&ei[e]);
    int d = __ldg(&ei[NEDGES + e]);
    float4 v = *(const float4*)(feat + (size_t)s * DFEAT + c * 4);
    float* p = dstbuf + (size_t)d * DFEAT + c * 4;
    asm volatile("red.global.add.v4.f32 [%0], {%1,%2,%3,%4};"
                 :: "l"(p), "f"(v.x), "f"(v.y), "f"(v.z), "f"(v.w) : "memory");
}

// ---------------- graph pooling ---------------------------------------------
__global__ void k_pool(const float* __restrict__ hfeat, const int* __restrict__ batch) {
    int idx = blockIdx.x * blockDim.x + threadIdx.x;
    if (idx >= N_NODES * 16) return;
    int n = idx >> 4, c = idx & 15;
    int g = __ldg(&batch[n]);
    float4 v = *(const float4*)(hfeat + (size_t)n * DFEAT + c * 4);
    float* p = g_pool + g * DFEAT + c * 4;
    asm volatile("red.global.add.v4.f32 [%0], {%1,%2,%3,%4};"
                 :: "l"(p), "f"(v.x), "f"(v.y), "f"(v.z), "f"(v.w) : "memory");
}

// ---------------- fused KAN 64->64 layer (packed f32x2) ----------------------
// 128-node tile, 256 threads. Thread (ng 0..31, og 0..7) handles node pairs
// p0=2ng (nodes 4ng,4ng+1), p1=2ng+1 (nodes 4ng+2,4ng+3) and outputs
// og*8..og*8+7. sFp: pair-interleaved F features [pair][k][2]. sW2: weights
// duplicated [physrow][k][2], physrow = (o&7)<<3 | o>>3.
__global__ __launch_bounds__(TPB, 2) void k_kan64(const float* __restrict__ yin,
                                                  float* __restrict__ hout,
                                                  const float* __restrict__ W2) {
    extern __shared__ float smem[];
    float* sW2 = smem;                     // 64 * 132
    float* sFp = smem + 64 * SW2_STRIDE;   // 64 * 132

    int tid = threadIdx.x;
    int nb = blockIdx.x * NTILE;
    int ng = tid >> 3;   // 0..31
    int og = tid & 7;    // 0..7

    unsigned long long acc2[2][8];
#pragma unroll
    for (int a = 0; a < 2; a++)
#pragma unroll
        for (int b = 0; b < 8; b++) acc2[a][b] = 0ull;

    // ---- stage chunk 0: W copy + silu features ----
    {
        const float4* Wc = (const float4*)W2;   // chunk 0
#pragma unroll
        for (int r = 0; r < 8; r++) {
            int idx = r * TPB + tid;            // 0..2047
            int row = idx >> 5, q = idx & 31;
            *(float4*)&sW2[row * SW2_STRIDE + q * 4] = Wc[idx];
        }
#pragma unroll
        for (int r = 0; r < 4; r++) {
            int idx = r * TPB + tid;            // 0..1023: (pair, colgroup)
            int p = idx >> 4, cg = idx & 15;
            int n0 = nb + 2 * p; if (n0 >= N_NODES) n0 = N_NODES - 1;
            int n1 = n0 + 1;     if (n1 >= N_NODES) n1 = N_NODES - 1;
            float4 a = *(const float4*)&yin[(size_t)n0 * DFEAT + cg * 4];
            float4 b = *(const float4*)&yin[(size_t)n1 * DFEAT + cg * 4];
            float4 v0 = make_float4(silu_f(a.x), silu_f(b.x), silu_f(a.y), silu_f(b.y));
            float4 v1 = make_float4(silu_f(a.z), silu_f(b.z), silu_f(a.w), silu_f(b.w));
            *(float4*)&sFp[p * SFP_STRIDE + cg * 8]     = v0;
            *(float4*)&sFp[p * SFP_STRIDE + cg * 8 + 4] = v1;
        }
    }

    // prefetch y values for chunk 1 (spline inputs)
    float pf[4];
#pragma unroll
    for (int t = 0; t < 2; t++) {
        int idx = t * TPB + tid;                // (pair, ii)
        int p = idx >> 3, ii = idx & 7;
        int n0 = nb + 2 * p; if (n0 >= N_NODES) n0 = N_NODES - 1;
        int n1 = n0 + 1;     if (n1 >= N_NODES) n1 = N_NODES - 1;
        pf[2 * t]     = yin[(size_t)n0 * DFEAT + ii];
        pf[2 * t + 1] = yin[(size_t)n1 * DFEAT + ii];
    }

    for (int kc = 0; kc < KCHUNKS; kc++) {
        __syncthreads();

        // ---- GEMM over this 64-wide K chunk ----
        const float* fp0 = &sFp[(2 * ng) * SFP_STRIDE];
        const float* fp1 = &sFp[(2 * ng + 1) * SFP_STRIDE];
        const float* wp  = &sW2[og * SW2_STRIDE];
#pragma unroll 8
        for (int k = 0; k < 64; k += 2) {
            ulonglong2 f0 = *(const ulonglong2*)&fp0[k * 2];
            ulonglong2 f1 = *(const ulonglong2*)&fp1[k * 2];
#pragma unroll
            for (int oo = 0; oo < 8; oo++) {
                ulonglong2 w = *(const ulonglong2*)&wp[oo * 8 * SW2_STRIDE + k * 2];
                FMA2(acc2[0][oo], f0.x, w.x);
                FMA2(acc2[0][oo], f0.y, w.y);
                FMA2(acc2[1][oo], f1.x, w.x);
                FMA2(acc2[1][oo], f1.y, w.y);
            }
        }

        if (kc < KCHUNKS - 1) {
            __syncthreads();   // all GEMM readers done before restage
            // stage W chunk kc+1
            const float4* Wc = (const float4*)(W2 + (kc + 1) * 64 * 128);
#pragma unroll
            for (int r = 0; r < 8; r++) {
                int idx = r * TPB + tid;
                int row = idx >> 5, q = idx & 31;
                *(float4*)&sW2[row * SW2_STRIDE + q * 4] = Wc[idx];
            }
            // stage spline features for chunk kc+1 from prefetched y
#pragma unroll
            for (int t = 0; t < 2; t++) {
                int idx = t * TPB + tid;
                int p = idx >> 3, ii = idx & 7;
                float p0 = (pf[2 * t]     + 2.2f) * 2.5f;
                float p1 = (pf[2 * t + 1] + 2.2f) * 2.5f;
                float* dst = &sFp[p * SFP_STRIDE + ii * 16];
#pragma unroll
                for (int g = 0; g < 8; g++) {
                    float2 v = make_float2(n3(p0 - (float)g), n3(p1 - (float)g));
                    *(float2*)&dst[g * 2] = v;
                }
            }
            // prefetch y for chunk kc+2
            if (kc < KCHUNKS - 2) {
#pragma unroll
                for (int t = 0; t < 2; t++) {
                    int idx = t * TPB + tid;
                    int p = idx >> 3, ii = idx & 7;
                    int n0 = nb + 2 * p; if (n0 >= N_NODES) n0 = N_NODES - 1;
                    int n1 = n0 + 1;     if (n1 >= N_NODES) n1 = N_NODES - 1;
                    pf[2 * t]     = yin[(size_t)n0 * DFEAT + (kc + 1) * 8 + ii];
                    pf[2 * t + 1] = yin[(size_t)n1 * DFEAT + (kc + 1) * 8 + ii];
                }
            }
        }
    }

    // ---- store: unpack f32x2 accumulators ----
#pragma unroll
    for (int pi = 0; pi < 2; pi++) {
        float lo[8], hi[8];
#pragma unroll
        for (int oo = 0; oo < 8; oo++) {
            lo[oo] = __uint_as_float((uint32_t)(acc2[pi][oo] & 0xffffffffull));
            hi[oo] = __uint_as_float((uint32_t)(acc2[pi][oo] >> 32));
        }
        int gn0 = nb + 4 * ng + 2 * pi;
        if (gn0 < N_NODES) {
            *(float4*)(hout + (size_t)gn0 * DFEAT + og * 8)     = make_float4(lo[0], lo[1], lo[2], lo[3]);
            *(float4*)(hout + (size_t)gn0 * DFEAT + og * 8 + 4) = make_float4(lo[4], lo[5], lo[6], lo[7]);
        }
        if (gn0 + 1 < N_NODES) {
            *(float4*)(hout + (size_t)(gn0 + 1) * DFEAT + og * 8)     = make_float4(hi[0], hi[1], hi[2], hi[3]);
            *(float4*)(hout + (size_t)(gn0 + 1) * DFEAT + og * 8 + 4) = make_float4(hi[4], hi[5], hi[6], hi[7]);
        }
    }
}

// ---------------- KAN head 64 -> 10 over pooled graphs ----------------------
__global__ void k_head(float* __restrict__ out) {
    __shared__ float sF[KTOT];
    int g = blockIdx.x;
    int t = threadIdx.x;  // 64 threads
    float v = g_pool[g * DFEAT + t];
    sF[t] = silu_f(v);
    float p = (v + 2.2f) * 2.5f;
#pragma unroll
    for (int gg = 0; gg < 8; gg++) sF[DFEAT + t * 8 + gg] = n3(p - (float)gg);
    __syncthreads();
    if (t < NTARG) {
        const float* w = g_Wh + t * KTOT;
        float acc = 0.0f;
#pragma unroll 8
        for (int k = 0; k < KTOT; k++) acc += sF[k] * w[k];
        out[g * NTARG + t] = acc;
    }
}

// ---------------- launch -----------------------------------------------------
extern "C" void kernel_launch(void* const* d_in, const int* in_sizes, int n_in,
                              void* d_out, int out_size) {
    const float* x      = (const float*)d_in[0];
    const int*   ei     = (const int*)d_in[1];
    const int*   batch  = (const int*)d_in[2];
    const float* bw0    = (const float*)d_in[3];
    const float* sw0    = (const float*)d_in[4];
    const float* sc0    = (const float*)d_in[5];
    const float* bw1    = (const float*)d_in[6];
    const float* sw1    = (const float*)d_in[7];
    const float* sc1    = (const float*)d_in[8];
    const float* bwh    = (const float*)d_in[9];
    const float* swh    = (const float*)d_in[10];
    const float* sch    = (const float*)d_in[11];
    float* out = (float*)d_out;

    float *p_y, *p_h, *p_y2, *p_pool, *p_W2;
    cudaGetSymbolAddress((void**)&p_y,    g_y);
    cudaGetSymbolAddress((void**)&p_h,    g_h);
    cudaGetSymbolAddress((void**)&p_y2,   g_y2);
    cudaGetSymbolAddress((void**)&p_pool, g_pool);
    cudaGetSymbolAddress((void**)&p_W2,   g_W2);

    cudaFuncSetAttribute(k_kan64, cudaFuncAttributeMaxDynamicSharedMemorySize, KAN_SMEM);

    const int n4 = N_NODES * DFEAT / 4;
    const int scat_blocks = (NEDGES * 16 + 255) / 256;
    const int kan_blocks = (N_NODES + NTILE - 1) / NTILE;

    k_prep<<<(DFEAT * KTOT + 255) / 256, 256>>>(bw0, sw0, sc0, bw1, sw1, sc1, bwh, swh, sch);

    // layer 0
    k_copy4<<<(n4 + 255) / 256, 256>>>((float4*)p_y, (const float4*)x, n4);
    k_scatter<<<scat_blocks, 256>>>(x, p_y, ei);
    k_kan64<<<kan_blocks, TPB, KAN_SMEM>>>(p_y, p_h, p_W2);

    // layer 1
    k_copy4<<<(n4 + 255) / 256, 256>>>((float4*)p_y2, (const float4*)p_h, n4);
    k_scatter<<<scat_blocks, 256>>>(p_h, p_y2, ei);
    k_kan64<<<kan_blocks, TPB, KAN_SMEM>>>(p_y2, p_y, p_W2 + KCHUNKS * 64 * 128);

    // pool + head
    k_zero<<<(NGRAPHS * DFEAT + 255) / 256, 256>>>(p_pool, NGRAPHS * DFEAT);
    k_pool<<<(N_NODES * 16 + 255) / 256, 256>>>(p_y, batch);
    k_head<<<NGRAPHS, DFEAT>>>(out);
}

// round 7
// speedup vs baseline: 1.0401x; 1.0401x over previous
#include <cuda_runtime.h>
#include <cstdint>

#define N_NODES 100000
#define DFEAT   64
#define NCOEF   8
#define KTOT    576
#define NGRAPHS 512
#define NTARG   10
#define NEDGES  1200000

#define NTILE     256          // nodes per CTA
#define TPB       256
#define KCHUNKS   9
#define SF_STRIDE 68           // floats per node row (272B: 16B-aligned, 16 mod 128)
#define SWP_STRIDE 132         // floats per pair row (528B: 16B-aligned, 16 mod 128)
#define KAN_SMEM  ((32 * SWP_STRIDE + NTILE * SF_STRIDE) * 4)   // 86528 B

// ---------------- static device scratch -------------------------------------
__device__ __align__(128) float g_y [N_NODES * DFEAT];
__device__ __align__(128) float g_h [N_NODES * DFEAT];
__device__ __align__(128) float g_y2[N_NODES * DFEAT];
__device__ __align__(128) float g_pool[NGRAPHS * DFEAT];
__device__ __align__(128) float g_Wh[NTARG * KTOT];
// pair-interleaved weights: [layer][chunk][32 phys pair-rows][128 floats]
// phys row = j*8 + og holds outs (og*8+2j, og*8+2j+1) interleaved per k.
__device__ __align__(128) float g_Wp[2][KCHUNKS][32 * 128];

// ---------------- math helpers ----------------------------------------------
__device__ __forceinline__ float silu_f(float v) { return v / (1.0f + __expf(-v)); }

// cardinal cubic B-spline, support (0,4): basis g value at p is n3(p - g)
// grid t_j = (j-3)*0.4 - 1  ->  p = (x + 2.2) * 2.5
__device__ __forceinline__ float n3(float t) {
    float r = 0.0f;
    if (t > 0.0f && t < 4.0f) {
        if (t < 1.0f)      { r = t * t * t * (1.0f / 6.0f); }
        else if (t < 2.0f) { float u = t - 1.0f; r = (1.0f + 3.0f*u + 3.0f*u*u - 3.0f*u*u*u) * (1.0f/6.0f); }
        else if (t < 3.0f) { float u = t - 2.0f; r = (4.0f - 6.0f*u*u + 3.0f*u*u*u) * (1.0f/6.0f); }
        else               { float u = 4.0f - t; r = u * u * u * (1.0f/6.0f); }
    }
    return r;
}

// packed f32x2 FMA: acc = a*b + acc (full fp32 per lane)
#define FMA2(acc, a, b) \
    asm("fma.rn.f32x2 %0, %1, %2, %0;" : "+l"(acc) : "l"(a), "l"(b))
// duplicate one f32 into both lanes of a 64-bit pair
#define DUP2(d, f) \
    asm("mov.b64 %0, {%1, %1};" : "=l"(d) : "r"(__float_as_uint(f)))

// ---------------- weight prep: pair-interleaved W_eff -----------------------
__global__ void k_prep(const float* __restrict__ bw0, const float* __restrict__ sw0, const float* __restrict__ sc0,
                       const float* __restrict__ bw1, const float* __restrict__ sw1, const float* __restrict__ sc1,
                       const float* __restrict__ bwh, const float* __restrict__ swh, const float* __restrict__ sch) {
    int idx = blockIdx.x * blockDim.x + threadIdx.x;
    if (idx >= DFEAT * KTOT) return;
    int o = idx / KTOT, k = idx % KTOT;
    float v0, v1;
    if (k < DFEAT) {
        v0 = bw0[o * DFEAT + k];
        v1 = bw1[o * DFEAT + k];
    } else {
        int k2 = k - DFEAT;
        int i = k2 >> 3, g = k2 & 7;
        v0 = sw0[(o * DFEAT + i) * NCOEF + g] * sc0[o * DFEAT + i];
        v1 = sw1[(o * DFEAT + i) * NCOEF + g] * sc1[o * DFEAT + i];
    }
    int chunk = k >> 6, kk = k & 63;
    int og = o >> 3, j = (o & 7) >> 1, lo = o & 1;
    int pos = (j * 8 + og) * 128 + kk * 2 + lo;
    g_Wp[0][chunk][pos] = v0;
    g_Wp[1][chunk][pos] = v1;
    if (o < NTARG) {
        float vh;
        if (k < DFEAT) {
            vh = bwh[o * DFEAT + k];
        } else {
            int k2 = k - DFEAT;
            int i = k2 >> 3, g = k2 & 7;
            vh = swh[(o * DFEAT + i) * NCOEF + g] * sch[o * DFEAT + i];
        }
        g_Wh[o * KTOT + k] = vh;
    }
}

// ---------------- utility kernels -------------------------------------------
__global__ void k_copy4(float4* __restrict__ dst, const float4* __restrict__ src, int n4) {
    int i = blockIdx.x * blockDim.x + threadIdx.x;
    if (i < n4) dst[i] = src[i];
}
__global__ void k_zero(float* __restrict__ dst, int n) {
    int i = blockIdx.x * blockDim.x + threadIdx.x;
    if (i < n) dst[i] = 0.0f;
}

// ---------------- edge scatter: dstbuf[dst] += feat[src] --------------------
__global__ void k_scatter(const float* __restrict__ feat, float* __restrict__ dstbuf,
                          const int* __restrict__ ei) {
    int idx = blockIdx.x * blockDim.x + threadIdx.x;
    if (idx >= NEDGES * 16) return;
    int e = idx >> 4;
    int c = idx & 15;
    int s = __ldg(&ei[e]);
    int d = __ldg(&ei[NEDGES + e]);
    float4 v = *(const float4*)(feat + (size_t)s * DFEAT + c * 4);
    float* p = dstbuf + (size_t)d * DFEAT + c * 4;
    asm volatile("red.global.add.v4.f32 [%0], {%1,%2,%3,%4};"
                 :: "l"(p), "f"(v.x), "f"(v.y), "f"(v.z), "f"(v.w) : "memory");
}

// ---------------- graph pooling ---------------------------------------------
__global__ void k_pool(const float* __restrict__ hfeat, const int* __restrict__ batch) {
    int idx = blockIdx.x * blockDim.x + threadIdx.x;
    if (idx >= N_NODES * 16) return;
    int n = idx >> 4, c = idx & 15;
    int g = __ldg(&batch[n]);
    float4 v = *(const float4*)(hfeat + (size_t)n * DFEAT + c * 4);
    float* p = g_pool + g * DFEAT + c * 4;
    asm volatile("red.global.add.v4.f32 [%0], {%1,%2,%3,%4};"
                 :: "l"(p), "f"(v.x), "f"(v.y), "f"(v.z), "f"(v.w) : "memory");
}

// ---------------- fused KAN 64->64 layer (FFMA2, 8x8 tile) ------------------
// 256-node tile, 256 threads. Thread (ng 0..31, og 0..7) handles nodes
// {nn*32+ng : nn=0..7} and outputs og*8..og*8+7 as 4 FMA2 pairs.
// sF: per-node rows, stride 68 (warp's 4 consecutive ng rows -> offsets
// {0,16,32,48} mod 128: conflict-free). sWp: 32 pair rows, phys row j*8+og,
// stride 132 (8 og rows -> offsets {0,16,...,112} mod 128: conflict-free).
__global__ __launch_bounds__(TPB, 2) void k_kan64(const float* __restrict__ yin,
                                                  float* __restrict__ hout,
                                                  const float* __restrict__ Wp) {
    extern __shared__ float smem[];
    float* sWp = smem;                     // 32 * 132
    float* sF  = smem + 32 * SWP_STRIDE;   // 256 * 68

    int tid = threadIdx.x;
    int nb = blockIdx.x * NTILE;
    int ng = tid >> 3;   // 0..31
    int og = tid & 7;    // 0..7

    unsigned long long acc2[8][4];
#pragma unroll
    for (int a = 0; a < 8; a++)
#pragma unroll
        for (int b = 0; b < 4; b++) acc2[a][b] = 0ull;

    for (int kc = 0; kc < KCHUNKS; kc++) {
        __syncthreads();   // previous GEMM readers done before restage

        // ---- stage W chunk: 1024 float4 with stride insertion ----
        {
            const float4* Wc = (const float4*)(Wp + kc * 32 * 128);
#pragma unroll
            for (int r = 0; r < 4; r++) {
                int idx = r * TPB + tid;           // 0..1023
                int row = idx >> 5, q = idx & 31;
                *(float4*)&sWp[row * SWP_STRIDE + q * 4] = Wc[idx];
            }
        }
        // ---- stage F chunk ----
        if (kc == 0) {
#pragma unroll
            for (int r = 0; r < 16; r++) {
                int idx = r * TPB + tid;           // 0..4095 float4 units
                int n = idx >> 4, cg = idx & 15;
                int gn = nb + n; if (gn >= N_NODES) gn = N_NODES - 1;
                float4 v = *(const float4*)&yin[(size_t)gn * DFEAT + cg * 4];
                float4 s;
                s.x = silu_f(v.x); s.y = silu_f(v.y);
                s.z = silu_f(v.z); s.w = silu_f(v.w);
                *(float4*)&sF[n * SF_STRIDE + cg * 4] = s;
            }
        } else {
#pragma unroll
            for (int r = 0; r < 8; r++) {
                int idx = r * TPB + tid;           // 0..2047: (n, ii)
                int n = idx >> 3, ii = idx & 7;
                int gn = nb + n; if (gn >= N_NODES) gn = N_NODES - 1;
                float v = yin[(size_t)gn * DFEAT + (kc - 1) * 8 + ii];
                float p = (v + 2.2f) * 2.5f;
                float* dst = &sF[n * SF_STRIDE + ii * 8];
#pragma unroll
                for (int g = 0; g < 8; g++) dst[g] = n3(p - (float)g);
            }
        }
        __syncthreads();

        // ---- GEMM over this 64-wide K chunk ----
#pragma unroll 4
        for (int k = 0; k < 64; k += 4) {
            // weight pairs: 4 j-rows x 2 ulonglong2 (covers k..k+3)
            ulonglong2 wa[4], wb[4];
#pragma unroll
            for (int j = 0; j < 4; j++) {
                const float* wr = &sWp[(j * 8 + og) * SWP_STRIDE + k * 2];
                wa[j] = *(const ulonglong2*)wr;        // pairs for k, k+1
                wb[j] = *(const ulonglong2*)(wr + 4);  // pairs for k+2, k+3
            }
#pragma unroll
            for (int nn = 0; nn < 8; nn++) {
                float4 f = *(const float4*)&sF[(nn * 32 + ng) * SF_STRIDE + k];
                unsigned long long d0, d1, d2, d3;
                DUP2(d0, f.x); DUP2(d1, f.y); DUP2(d2, f.z); DUP2(d3, f.w);
#pragma unroll
                for (int j = 0; j < 4; j++) {
                    FMA2(acc2[nn][j], d0, wa[j].x);
                    FMA2(acc2[nn][j], d1, wa[j].y);
                    FMA2(acc2[nn][j], d2, wb[j].x);
                    FMA2(acc2[nn][j], d3, wb[j].y);
                }
            }
        }
    }

    // ---- store: acc2[nn][j] = outs (og*8+2j, og*8+2j+1) for node nn*32+ng ----
#pragma unroll
    for (int nn = 0; nn < 8; nn++) {
        int gn = nb + nn * 32 + ng;
        if (gn < N_NODES) {
            float o0 = __uint_as_float((uint32_t)(acc2[nn][0] & 0xffffffffull));
            float o1 = __uint_as_float((uint32_t)(acc2[nn][0] >> 32));
            float o2 = __uint_as_float((uint32_t)(acc2[nn][1] & 0xffffffffull));
            float o3 = __uint_as_float((uint32_t)(acc2[nn][1] >> 32));
            float o4 = __uint_as_float((uint32_t)(acc2[nn][2] & 0xffffffffull));
            float o5 = __uint_as_float((uint32_t)(acc2[nn][2] >> 32));
            float o6 = __uint_as_float((uint32_t)(acc2[nn][3] & 0xffffffffull));
            float o7 = __uint_as_float((uint32_t)(acc2[nn][3] >> 32));
            *(float4*)(hout + (size_t)gn * DFEAT + og * 8)     = make_float4(o0, o1, o2, o3);
            *(float4*)(hout + (size_t)gn * DFEAT + og * 8 + 4) = make_float4(o4, o5, o6, o7);
        }
    }
}

// ---------------- KAN head 64 -> 10 over pooled graphs ----------------------
__global__ void k_head(float* __restrict__ out) {
    __shared__ float sF[KTOT];
    int g = blockIdx.x;
    int t = threadIdx.x;  // 64 threads
    float v = g_pool[g * DFEAT + t];
    sF[t] = silu_f(v);
    float p = (v + 2.2f) * 2.5f;
#pragma unroll
    for (int gg = 0; gg < 8; gg++) sF[DFEAT + t * 8 + gg] = n3(p - (float)gg);
    __syncthreads();
    if (t < NTARG) {
        const float* w = g_Wh + t * KTOT;
        float acc = 0.0f;
#pragma unroll 8
        for (int k = 0; k < KTOT; k++) acc += sF[k] * w[k];
        out[g * NTARG + t] = acc;
    }
}

// ---------------- launch -----------------------------------------------------
extern "C" void kernel_launch(void* const* d_in, const int* in_sizes, int n_in,
                              void* d_out, int out_size) {
    const float* x      = (const float*)d_in[0];
    const int*   ei     = (const int*)d_in[1];
    const int*   batch  = (const int*)d_in[2];
    const float* bw0    = (const float*)d_in[3];
    const float* sw0    = (const float*)d_in[4];
    const float* sc0    = (const float*)d_in[5];
    const float* bw1    = (const float*)d_in[6];
    const float* sw1    = (const float*)d_in[7];
    const float* sc1    = (const float*)d_in[8];
    const float* bwh    = (const float*)d_in[9];
    const float* swh    = (const float*)d_in[10];
    const float* sch    = (const float*)d_in[11];
    float* out = (float*)d_out;

    float *p_y, *p_h, *p_y2, *p_pool, *p_Wp;
    cudaGetSymbolAddress((void**)&p_y,    g_y);
    cudaGetSymbolAddress((void**)&p_h,    g_h);
    cudaGetSymbolAddress((void**)&p_y2,   g_y2);
    cudaGetSymbolAddress((void**)&p_pool, g_pool);
    cudaGetSymbolAddress((void**)&p_Wp,   g_Wp);

    cudaFuncSetAttribute(k_kan64, cudaFuncAttributeMaxDynamicSharedMemorySize, KAN_SMEM);

    const int n4 = N_NODES * DFEAT / 4;
    const int scat_blocks = (NEDGES * 16 + 255) / 256;
    const int kan_blocks = (N_NODES + NTILE - 1) / NTILE;

    k_prep<<<(DFEAT * KTOT + 255) / 256, 256>>>(bw0, sw0, sc0, bw1, sw1, sc1, bwh, swh, sch);

    // layer 0
    k_copy4<<<(n4 + 255) / 256, 256>>>((float4*)p_y, (const float4*)x, n4);
    k_scatter<<<scat_blocks, 256>>>(x, p_y, ei);
    k_kan64<<<kan_blocks, TPB, KAN_SMEM>>>(p_y, p_h, p_Wp);

    // layer 1
    k_copy4<<<(n4 + 255) / 256, 256>>>((float4*)p_y2, (const float4*)p_h, n4);
    k_scatter<<<scat_blocks, 256>>>(p_h, p_y2, ei);
    k_kan64<<<kan_blocks, TPB, KAN_SMEM>>>(p_y2, p_y, p_Wp + KCHUNKS * 32 * 128);

    // pool + head
    k_zero<<<(NGRAPHS * DFEAT + 255) / 256, 256>>>(p_pool, NGRAPHS * DFEAT);
    k_pool<<<(N_NODES * 16 + 255) / 256, 256>>>(p_y, batch);
    k_head<<<NGRAPHS, DFEAT>>>(out);
}

// round 8
// speedup vs baseline: 1.1114x; 1.0686x over previous
#include <cuda_runtime.h>
#include <cstdint>

#define N_NODES 100000
#define DFEAT   64
#define NCOEF   8
#define KTOT    576
#define NGRAPHS 512
#define NTARG   10
#define NEDGES  1200000

#define NTILE     128        // nodes per block in k_kan64
#define TPB       256
#define SF_STRIDE 68         // 272B rows: 16B aligned; warp-adjacent rows 16 banks apart
#define SW_STRIDE 68
#define KAN_SMEM  ((64 * SW_STRIDE + NTILE * SF_STRIDE) * 4)   // 52224 B

// ---------------- static device scratch (no allocation allowed) -------------
__device__ __align__(128) float g_y [N_NODES * DFEAT];
__device__ __align__(128) float g_h [N_NODES * DFEAT];
__device__ __align__(128) float g_y2[N_NODES * DFEAT];
__device__ __align__(128) float g_pool[NGRAPHS * DFEAT];
__device__ __align__(128) float g_W0[DFEAT * KTOT];
__device__ __align__(128) float g_W1[DFEAT * KTOT];
__device__ __align__(128) float g_Wh[NTARG * KTOT];

__device__ __forceinline__ float silu_f(float v) {
    return v / (1.0f + __expf(-v));
}

// closed-form uniform cubic B-spline: write the 8 basis values to dst[0..7].
// grid: t_j = (j-3)*0.4 - 1, j=0..11; support [-2.2, 2.2)
__device__ __forceinline__ void bspl8_store(float x, float* dst) {
    // vectorized zero-fill (dst is 16B-aligned: row base 272B*n + 32B*ii)
    *(float4*)dst       = make_float4(0.f, 0.f, 0.f, 0.f);
    *(float4*)(dst + 4) = make_float4(0.f, 0.f, 0.f, 0.f);
    float p = (x + 2.2f) * 2.5f;
    if (p >= 0.0f && p < 11.0f) {
        int c = (int)p;            // cell index 0..10
        float u  = p - (float)c;
        float um = 1.0f - u;
        float u2 = u * u;
        float u3 = u2 * u;
        float w_s0 = u3 * (1.0f / 6.0f);                                        // B_c
        float w_s1 = (1.0f + 3.0f * u + 3.0f * u2 - 3.0f * u3) * (1.0f / 6.0f); // B_{c-1}
        float w_s2 = (4.0f - 6.0f * u2 + 3.0f * u3) * (1.0f / 6.0f);            // B_{c-2}
        float w_s3 = um * um * um * (1.0f / 6.0f);                              // B_{c-3}
        if (c     <= 7)               dst[c]     = w_s0;
        if (c - 1 >= 0 && c - 1 <= 7) dst[c - 1] = w_s1;
        if (c - 2 >= 0 && c - 2 <= 7) dst[c - 2] = w_s2;
        if (c - 3 >= 0)               dst[c - 3] = w_s3;
    }
}

__device__ __forceinline__ void bspl8_reg(float x, float b[8]) {
    float tmp[8];
    bspl8_store(x, tmp);
#pragma unroll
    for (int g = 0; g < 8; g++) b[g] = tmp[g];
}

// ---------------- weight prep: W_eff[o][k] ----------------------------------
__global__ void k_prep(const float* __restrict__ bw0, const float* __restrict__ sw0, const float* __restrict__ sc0,
                       const float* __restrict__ bw1, const float* __restrict__ sw1, const float* __restrict__ sc1,
                       const float* __restrict__ bwh, const float* __restrict__ swh, const float* __restrict__ sch) {
    int idx = blockIdx.x * blockDim.x + threadIdx.x;
    if (idx >= DFEAT * KTOT) return;
    int o = idx / KTOT, k = idx % KTOT;
    float v0, v1;
    if (k < DFEAT) {
        v0 = bw0[o * DFEAT + k];
        v1 = bw1[o * DFEAT + k];
    } else {
        int k2 = k - DFEAT;
        int i = k2 >> 3, g = k2 & 7;
        v0 = sw0[(o * DFEAT + i) * NCOEF + g] * sc0[o * DFEAT + i];
        v1 = sw1[(o * DFEAT + i) * NCOEF + g] * sc1[o * DFEAT + i];
    }
    g_W0[idx] = v0;
    g_W1[idx] = v1;
    if (o < NTARG) {
        float vh;
        if (k < DFEAT) {
            vh = bwh[o * DFEAT + k];
        } else {
            int k2 = k - DFEAT;
            int i = k2 >> 3, g = k2 & 7;
            vh = swh[(o * DFEAT + i) * NCOEF + g] * sch[o * DFEAT + i];
        }
        g_Wh[o * KTOT + k] = vh;
    }
}

// ---------------- utility kernels -------------------------------------------
__global__ void k_copy4(float4* __restrict__ dst, const float4* __restrict__ src, int n4) {
    int i = blockIdx.x * blockDim.x + threadIdx.x;
    if (i < n4) dst[i] = src[i];
}

__global__ void k_zero(float* __restrict__ dst, int n) {
    int i = blockIdx.x * blockDim.x + threadIdx.x;
    if (i < n) dst[i] = 0.0f;
}

// ---------------- edge scatter: dstbuf[dst] += feat[src] --------------------
__global__ void k_scatter(const float* __restrict__ feat, float* __restrict__ dstbuf,
                          const int* __restrict__ ei) {
    int idx = blockIdx.x * blockDim.x + threadIdx.x;
    if (idx >= NEDGES * 16) return;
    int e = idx >> 4;
    int c = idx & 15;
    int s = __ldg(&ei[e]);
    int d = __ldg(&ei[NEDGES + e]);
    float4 v = *(const float4*)(feat + (size_t)s * DFEAT + c * 4);
    float* p = dstbuf + (size_t)d * DFEAT + c * 4;
    asm volatile("red.global.add.v4.f32 [%0], {%1,%2,%3,%4};"
                 :: "l"(p), "f"(v.x), "f"(v.y), "f"(v.z), "f"(v.w)
                 : "memory");
}

// ---------------- graph pooling ---------------------------------------------
__global__ void k_pool(const float* __restrict__ hfeat, const int* __restrict__ batch) {
    int idx = blockIdx.x * blockDim.x + threadIdx.x;
    if (idx >= N_NODES * 16) return;
    int n = idx >> 4, c = idx & 15;
    int g = __ldg(&batch[n]);
    float4 v = *(const float4*)(hfeat + (size_t)n * DFEAT + c * 4);
    float* p = g_pool + g * DFEAT + c * 4;
    asm volatile("red.global.add.v4.f32 [%0], {%1,%2,%3,%4};"
                 :: "l"(p), "f"(v.x), "f"(v.y), "f"(v.z), "f"(v.w)
                 : "memory");
}

// ---------------- fused KAN 64->64 layer (R4 core + LDG prefetch) -----------
// 128-node tile, 256 threads, thread tile 4 nodes x 8 outs (interleaved node
// map: thread (ng, og) covers nodes {ng, ng+32, ng+64, ng+96}).
// sF: stride 68 -> warp-consecutive ng rows land 16 banks apart, conflict-free.
// sW: rows permuted ((o&7)<<3 | o>>3), stride 68 -> the 8 per-oo addresses
// cover offsets {0,16,...,112} mod 128, conflict-free.
__global__ __launch_bounds__(TPB, 2) void k_kan64(const float* __restrict__ yin,
                                                  float* __restrict__ hout,
                                                  const float* __restrict__ W) {
    extern __shared__ float smem[];
    float* sW = smem;                    // 64 * 68
    float* sF = smem + 64 * SW_STRIDE;   // 128 * 68

    int tid = threadIdx.x;
    int nb = blockIdx.x * NTILE;

    float acc[4][8];
#pragma unroll
    for (int a = 0; a < 4; a++)
#pragma unroll
        for (int b = 0; b < 8; b++) acc[a][b] = 0.0f;

    int ng = tid >> 3;  // 0..31
    int og = tid & 7;   // 0..7 -> outs og*8 .. og*8+7

    for (int kc = 0; kc < 9; kc++) {
        // ---- prefetch this chunk's staging data BEFORE the barrier ----
        // (LDGs don't touch smem; overlap L2 latency with barrier wait)
        float4 wpre[4];
#pragma unroll
        for (int r = 0; r < 4; r++) {
            int idx = r * TPB + tid;         // 0..1023
            int o = idx >> 4, kq = idx & 15;
            wpre[r] = *(const float4*)&W[o * KTOT + kc * 64 + kq * 4];
        }
        float4 spre[8];   // chunk 0: raw y values (silu applied after barrier)
        float  fpre[4];   // chunks 1..8: spline inputs
        if (kc == 0) {
#pragma unroll
            for (int r = 0; r < 8; r++) {
                int idx = r * TPB + tid;     // 0..2047 float4 units
                int n = idx >> 4, kq = idx & 15;
                int gn = nb + n; if (gn >= N_NODES) gn = N_NODES - 1;
                spre[r] = *(const float4*)&yin[(size_t)gn * DFEAT + kq * 4];
            }
        } else {
#pragma unroll
            for (int r = 0; r < 4; r++) {
                int idx = r * TPB + tid;     // 0..1023 (n, ii)
                int n = idx >> 3, ii = idx & 7;
                int gn = nb + n; if (gn >= N_NODES) gn = N_NODES - 1;
                fpre[r] = yin[(size_t)gn * DFEAT + (kc - 1) * 8 + ii];
            }
        }

        __syncthreads();   // previous GEMM readers done

        // ---- store staged data to smem ----
#pragma unroll
        for (int r = 0; r < 4; r++) {
            int idx = r * TPB + tid;
            int o = idx >> 4, kq = idx & 15;
            int pr = ((o & 7) << 3) | (o >> 3);
            *(float4*)&sW[pr * SW_STRIDE + kq * 4] = wpre[r];
        }
        if (kc == 0) {
#pragma unroll
            for (int r = 0; r < 8; r++) {
                int idx = r * TPB + tid;
                int n = idx >> 4, kq = idx & 15;
                float4 v = spre[r];
                float4 s;
                s.x = silu_f(v.x); s.y = silu_f(v.y);
                s.z = silu_f(v.z); s.w = silu_f(v.w);
                *(float4*)&sF[n * SF_STRIDE + kq * 4] = s;
            }
        } else {
#pragma unroll
            for (int r = 0; r < 4; r++) {
                int idx = r * TPB + tid;
                int n = idx >> 3, ii = idx & 7;
                bspl8_store(fpre[r], &sF[n * SF_STRIDE + ii * 8]);
            }
        }
        __syncthreads();

        // ---- GEMM over this 64-wide K chunk ----
#pragma unroll
        for (int k = 0; k < 64; k += 4) {
            float4 fv[4];
#pragma unroll
            for (int nn = 0; nn < 4; nn++)
                fv[nn] = *(const float4*)&sF[(nn * 32 + ng) * SF_STRIDE + k];
#pragma unroll
            for (int oo = 0; oo < 8; oo++) {
                float4 wv = *(const float4*)&sW[(oo * 8 + og) * SW_STRIDE + k];
#pragma unroll
                for (int nn = 0; nn < 4; nn++) {
                    acc[nn][oo] += fv[nn].x * wv.x + fv[nn].y * wv.y
                                 + fv[nn].z * wv.z + fv[nn].w * wv.w;
                }
            }
        }
    }

    // store: thread covers nodes nn*32+ng, outputs og*8..og*8+7
#pragma unroll
    for (int nn = 0; nn < 4; nn++) {
        int gn = nb + nn * 32 + ng;
        if (gn < N_NODES) {
            float4 v0 = make_float4(acc[nn][0], acc[nn][1], acc[nn][2], acc[nn][3]);
            float4 v1 = make_float4(acc[nn][4], acc[nn][5], acc[nn][6], acc[nn][7]);
            *(float4*)(hout + (size_t)gn * DFEAT + og * 8)     = v0;
            *(float4*)(hout + (size_t)gn * DFEAT + og * 8 + 4) = v1;
        }
    }
}

// ---------------- KAN head 64 -> 10 over pooled graphs ----------------------
__global__ void k_head(float* __restrict__ out) {
    __shared__ float sF[KTOT];
    int g = blockIdx.x;
    int t = threadIdx.x;  // 64 threads
    float v = g_pool[g * DFEAT + t];
    sF[t] = silu_f(v);
    float b[8];
    bspl8_reg(v, b);
#pragma unroll
    for (int gg = 0; gg < 8; gg++) sF[DFEAT + t * 8 + gg] = b[gg];
    __syncthreads();
    if (t < NTARG) {
        const float* w = g_Wh + t * KTOT;
        float acc = 0.0f;
#pragma unroll 8
        for (int k = 0; k < KTOT; k++) acc += sF[k] * w[k];
        out[g * NTARG + t] = acc;
    }
}

// ---------------- launch -----------------------------------------------------
extern "C" void kernel_launch(void* const* d_in, const int* in_sizes, int n_in,
                              void* d_out, int out_size) {
    const float* x      = (const float*)d_in[0];
    const int*   ei     = (const int*)d_in[1];
    const int*   batch  = (const int*)d_in[2];
    const float* bw0    = (const float*)d_in[3];
    const float* sw0    = (const float*)d_in[4];
    const float* sc0    = (const float*)d_in[5];
    const float* bw1    = (const float*)d_in[6];
    const float* sw1    = (const float*)d_in[7];
    const float* sc1    = (const float*)d_in[8];
    const float* bwh    = (const float*)d_in[9];
    const float* swh    = (const float*)d_in[10];
    const float* sch    = (const float*)d_in[11];
    float* out = (float*)d_out;

    float *p_y, *p_h, *p_y2, *p_pool, *p_W0, *p_W1;
    cudaGetSymbolAddress((void**)&p_y,    g_y);
    cudaGetSymbolAddress((void**)&p_h,    g_h);
    cudaGetSymbolAddress((void**)&p_y2,   g_y2);
    cudaGetSymbolAddress((void**)&p_pool, g_pool);
    cudaGetSymbolAddress((void**)&p_W0,   g_W0);
    cudaGetSymbolAddress((void**)&p_W1,   g_W1);

    cudaFuncSetAttribute(k_kan64, cudaFuncAttributeMaxDynamicSharedMemorySize, KAN_SMEM);

    const int n4 = N_NODES * DFEAT / 4;
    const int scat_blocks = (NEDGES * 16 + 255) / 256;
    const int kan_blocks = (N_NODES + NTILE - 1) / NTILE;

    k_prep<<<(DFEAT * KTOT + 255) / 256, 256>>>(bw0, sw0, sc0, bw1, sw1, sc1, bwh, swh, sch);

    // layer 0
    k_copy4<<<(n4 + 255) / 256, 256>>>((float4*)p_y, (const float4*)x, n4);
    k_scatter<<<scat_blocks, 256>>>(x, p_y, ei);
    k_kan64<<<kan_blocks, TPB, KAN_SMEM>>>(p_y, p_h, p_W0);

    // layer 1
    k_copy4<<<(n4 + 255) / 256, 256>>>((float4*)p_y2, (const float4*)p_h, n4);
    k_scatter<<<scat_blocks, 256>>>(p_h, p_y2, ei);
    k_kan64<<<kan_blocks, TPB, KAN_SMEM>>>(p_y2, p_y, p_W1);

    // pool + head
    k_zero<<<(NGRAPHS * DFEAT + 255) / 256, 256>>>(p_pool, NGRAPHS * DFEAT);
    k_pool<<<(N_NODES * 16 + 255) / 256, 256>>>(p_y, batch);
    k_head<<<NGRAPHS, DFEAT>>>(out);
}

// round 9
// speedup vs baseline: 1.1917x; 1.0723x over previous
#include <cuda_runtime.h>
#include <cstdint>

#define N_NODES 100000
#define DFEAT   64
#define NCOEF   8
#define KTOT    576
#define NGRAPHS 512
#define NTARG   10
#define NEDGES  1200000

#define NTILE     128        // nodes per block in k_kan64
#define TPB       256
#define SF_STRIDE 68         // 272B rows: 16B aligned; warp-adjacent rows 16 banks apart
#define SW_STRIDE 68
#define KAN_SMEM  ((64 * SW_STRIDE + NTILE * SF_STRIDE) * 4)   // 52224 B

// ---------------- static device scratch (no allocation allowed) -------------
__device__ __align__(128) float g_y [N_NODES * DFEAT];
__device__ __align__(128) float g_h [N_NODES * DFEAT];
__device__ __align__(128) float g_y2[N_NODES * DFEAT];
__device__ __align__(128) float g_pool[NGRAPHS * DFEAT];
__device__ __align__(128) float g_W0[DFEAT * KTOT];
__device__ __align__(128) float g_W1[DFEAT * KTOT];
__device__ __align__(128) float g_Wh[NTARG * KTOT];

__device__ __forceinline__ float silu_f(float v) {
    return v / (1.0f + __expf(-v));
}

// closed-form uniform cubic B-spline: write the 8 basis values to dst[0..7].
// grid: t_j = (j-3)*0.4 - 1, j=0..11; support [-2.2, 2.2)
__device__ __forceinline__ void bspl8_store(float x, float* dst) {
    *(float4*)dst       = make_float4(0.f, 0.f, 0.f, 0.f);
    *(float4*)(dst + 4) = make_float4(0.f, 0.f, 0.f, 0.f);
    float p = (x + 2.2f) * 2.5f;
    if (p >= 0.0f && p < 11.0f) {
        int c = (int)p;            // cell index 0..10
        float u  = p - (float)c;
        float um = 1.0f - u;
        float u2 = u * u;
        float u3 = u2 * u;
        float w_s0 = u3 * (1.0f / 6.0f);                                        // B_c
        float w_s1 = (1.0f + 3.0f * u + 3.0f * u2 - 3.0f * u3) * (1.0f / 6.0f); // B_{c-1}
        float w_s2 = (4.0f - 6.0f * u2 + 3.0f * u3) * (1.0f / 6.0f);            // B_{c-2}
        float w_s3 = um * um * um * (1.0f / 6.0f);                              // B_{c-3}
        if (c     <= 7)               dst[c]     = w_s0;
        if (c - 1 >= 0 && c - 1 <= 7) dst[c - 1] = w_s1;
        if (c - 2 >= 0 && c - 2 <= 7) dst[c - 2] = w_s2;
        if (c - 3 >= 0)               dst[c - 3] = w_s3;
    }
}

__device__ __forceinline__ void bspl8_reg(float x, float b[8]) {
    float tmp[8];
    bspl8_store(x, tmp);
#pragma unroll
    for (int g = 0; g < 8; g++) b[g] = tmp[g];
}

// ---------------- weight prep: W_eff[o][k] ----------------------------------
__global__ void k_prep(const float* __restrict__ bw0, const float* __restrict__ sw0, const float* __restrict__ sc0,
                       const float* __restrict__ bw1, const float* __restrict__ sw1, const float* __restrict__ sc1,
                       const float* __restrict__ bwh, const float* __restrict__ swh, const float* __restrict__ sch) {
    int idx = blockIdx.x * blockDim.x + threadIdx.x;
    if (idx >= DFEAT * KTOT) return;
    int o = idx / KTOT, k = idx % KTOT;
    float v0, v1;
    if (k < DFEAT) {
        v0 = bw0[o * DFEAT + k];
        v1 = bw1[o * DFEAT + k];
    } else {
        int k2 = k - DFEAT;
        int i = k2 >> 3, g = k2 & 7;
        v0 = sw0[(o * DFEAT + i) * NCOEF + g] * sc0[o * DFEAT + i];
        v1 = sw1[(o * DFEAT + i) * NCOEF + g] * sc1[o * DFEAT + i];
    }
    g_W0[idx] = v0;
    g_W1[idx] = v1;
    if (o < NTARG) {
        float vh;
        if (k < DFEAT) {
            vh = bwh[o * DFEAT + k];
        } else {
            int k2 = k - DFEAT;
            int i = k2 >> 3, g = k2 & 7;
            vh = swh[(o * DFEAT + i) * NCOEF + g] * sch[o * DFEAT + i];
        }
        g_Wh[o * KTOT + k] = vh;
    }
}

// ---------------- utility kernels -------------------------------------------
__global__ void k_copy4(float4* __restrict__ dst, const float4* __restrict__ src, int n4) {
    int i = blockIdx.x * blockDim.x + threadIdx.x;
    if (i < n4) dst[i] = src[i];
}

__global__ void k_zero(float* __restrict__ dst, int n) {
    int i = blockIdx.x * blockDim.x + threadIdx.x;
    if (i < n) dst[i] = 0.0f;
}

// ---------------- edge scatter: dstbuf[dst] += feat[src] --------------------
__global__ void k_scatter(const float* __restrict__ feat, float* __restrict__ dstbuf,
                          const int* __restrict__ ei) {
    int idx = blockIdx.x * blockDim.x + threadIdx.x;
    if (idx >= NEDGES * 16) return;
    int e = idx >> 4;
    int c = idx & 15;
    int s = __ldg(&ei[e]);
    int d = __ldg(&ei[NEDGES + e]);
    float4 v = *(const float4*)(feat + (size_t)s * DFEAT + c * 4);
    float* p = dstbuf + (size_t)d * DFEAT + c * 4;
    asm volatile("red.global.add.v4.f32 [%0], {%1,%2,%3,%4};"
                 :: "l"(p), "f"(v.x), "f"(v.y), "f"(v.z), "f"(v.w)
                 : "memory");
}

// ---------------- graph pooling ---------------------------------------------
__global__ void k_pool(const float* __restrict__ hfeat, const int* __restrict__ batch) {
    int idx = blockIdx.x * blockDim.x + threadIdx.x;
    if (idx >= N_NODES * 16) return;
    int n = idx >> 4, c = idx & 15;
    int g = __ldg(&batch[n]);
    float4 v = *(const float4*)(hfeat + (size_t)n * DFEAT + c * 4);
    float* p = g_pool + g * DFEAT + c * 4;
    asm volatile("red.global.add.v4.f32 [%0], {%1,%2,%3,%4};"
                 :: "l"(p), "f"(v.x), "f"(v.y), "f"(v.z), "f"(v.w)
                 : "memory");
}

// ---------------- fused KAN 64->64 layer (R4 core, 3 CTAs/SM) ---------------
// 128-node tile, 256 threads, thread tile 4 nodes x 8 outs (interleaved node
// map: thread (ng, og) covers nodes {ng, ng+32, ng+64, ng+96}).
// sF: stride 68 -> warp-consecutive ng rows land 16 banks apart, conflict-free.
// sW: rows permuted ((o&7)<<3 | o>>3), stride 68 -> the 8 per-oo addresses
// cover offsets {0,16,...,112} mod 128, conflict-free.
// hout2 (optional) receives a second copy of the result, fusing the next
// layer's aggregation-buffer initialization.
__global__ __launch_bounds__(TPB, 3) void k_kan64(const float* __restrict__ yin,
                                                  float* __restrict__ hout,
                                                  float* __restrict__ hout2,
                                                  const float* __restrict__ W) {
    extern __shared__ float smem[];
    float* sW = smem;                    // 64 * 68
    float* sF = smem + 64 * SW_STRIDE;   // 128 * 68

    int tid = threadIdx.x;
    int nb = blockIdx.x * NTILE;

    float acc[4][8];
#pragma unroll
    for (int a = 0; a < 4; a++)
#pragma unroll
        for (int b = 0; b < 8; b++) acc[a][b] = 0.0f;

    int ng = tid >> 3;  // 0..31
    int og = tid & 7;   // 0..7 -> outs og*8 .. og*8+7

    for (int kc = 0; kc < 9; kc++) {
        __syncthreads();
        // stage W chunk: 1024 float4, row-permuted
#pragma unroll
        for (int r = 0; r < 4; r++) {
            int idx = r * TPB + tid;         // 0..1023
            int o = idx >> 4, kq = idx & 15;
            float4 wv4 = *(const float4*)&W[o * KTOT + kc * 64 + kq * 4];
            int pr = ((o & 7) << 3) | (o >> 3);
            *(float4*)&sW[pr * SW_STRIDE + kq * 4] = wv4;
        }
        // stage F chunk
        if (kc == 0) {
#pragma unroll
            for (int r = 0; r < 8; r++) {
                int idx = r * TPB + tid;     // 0..2047 float4 units
                int n = idx >> 4, kq = idx & 15;
                int gn = nb + n; if (gn >= N_NODES) gn = N_NODES - 1;
                float4 v = *(const float4*)&yin[(size_t)gn * DFEAT + kq * 4];
                float4 s;
                s.x = silu_f(v.x); s.y = silu_f(v.y);
                s.z = silu_f(v.z); s.w = silu_f(v.w);
                *(float4*)&sF[n * SF_STRIDE + kq * 4] = s;
            }
        } else {
#pragma unroll
            for (int r = 0; r < 4; r++) {
                int idx = r * TPB + tid;     // 0..1023 (n, ii)
                int n = idx >> 3, ii = idx & 7;
                int gn = nb + n; if (gn >= N_NODES) gn = N_NODES - 1;
                float v = yin[(size_t)gn * DFEAT + (kc - 1) * 8 + ii];
                bspl8_store(v, &sF[n * SF_STRIDE + ii * 8]);
            }
        }
        __syncthreads();

        // GEMM over this 64-wide K chunk
#pragma unroll
        for (int k = 0; k < 64; k += 4) {
            float4 fv[4];
#pragma unroll
            for (int nn = 0; nn < 4; nn++)
                fv[nn] = *(const float4*)&sF[(nn * 32 + ng) * SF_STRIDE + k];
#pragma unroll
            for (int oo = 0; oo < 8; oo++) {
                float4 wv = *(const float4*)&sW[(oo * 8 + og) * SW_STRIDE + k];
#pragma unroll
                for (int nn = 0; nn < 4; nn++) {
                    acc[nn][oo] += fv[nn].x * wv.x + fv[nn].y * wv.y
                                 + fv[nn].z * wv.z + fv[nn].w * wv.w;
                }
            }
        }
    }

    // store: thread covers nodes nn*32+ng, outputs og*8..og*8+7
#pragma unroll
    for (int nn = 0; nn < 4; nn++) {
        int gn = nb + nn * 32 + ng;
        if (gn < N_NODES) {
            float4 v0 = make_float4(acc[nn][0], acc[nn][1], acc[nn][2], acc[nn][3]);
            float4 v1 = make_float4(acc[nn][4], acc[nn][5], acc[nn][6], acc[nn][7]);
            size_t base = (size_t)gn * DFEAT + og * 8;
            *(float4*)(hout + base)     = v0;
            *(float4*)(hout + base + 4) = v1;
            if (hout2) {
                *(float4*)(hout2 + base)     = v0;
                *(float4*)(hout2 + base + 4) = v1;
            }
        }
    }
}

// ---------------- KAN head 64 -> 10 over pooled graphs ----------------------
__global__ void k_head(float* __restrict__ out) {
    __shared__ float sF[KTOT];
    int g = blockIdx.x;
    int t = threadIdx.x;  // 64 threads
    float v = g_pool[g * DFEAT + t];
    sF[t] = silu_f(v);
    float b[8];
    bspl8_reg(v, b);
#pragma unroll
    for (int gg = 0; gg < 8; gg++) sF[DFEAT + t * 8 + gg] = b[gg];
    __syncthreads();
    if (t < NTARG) {
        const float* w = g_Wh + t * KTOT;
        float acc = 0.0f;
#pragma unroll 8
        for (int k = 0; k < KTOT; k++) acc += sF[k] * w[k];
        out[g * NTARG + t] = acc;
    }
}

// ---------------- launch -----------------------------------------------------
extern "C" void kernel_launch(void* const* d_in, const int* in_sizes, int n_in,
                              void* d_out, int out_size) {
    const float* x      = (const float*)d_in[0];
    const int*   ei     = (const int*)d_in[1];
    const int*   batch  = (const int*)d_in[2];
    const float* bw0    = (const float*)d_in[3];
    const float* sw0    = (const float*)d_in[4];
    const float* sc0    = (const float*)d_in[5];
    const float* bw1    = (const float*)d_in[6];
    const float* sw1    = (const float*)d_in[7];
    const float* sc1    = (const float*)d_in[8];
    const float* bwh    = (const float*)d_in[9];
    const float* swh    = (const float*)d_in[10];
    const float* sch    = (const float*)d_in[11];
    float* out = (float*)d_out;

    float *p_y, *p_h, *p_y2, *p_pool, *p_W0, *p_W1;
    cudaGetSymbolAddress((void**)&p_y,    g_y);
    cudaGetSymbolAddress((void**)&p_h,    g_h);
    cudaGetSymbolAddress((void**)&p_y2,   g_y2);
    cudaGetSymbolAddress((void**)&p_pool, g_pool);
    cudaGetSymbolAddress((void**)&p_W0,   g_W0);
    cudaGetSymbolAddress((void**)&p_W1,   g_W1);

    cudaFuncSetAttribute(k_kan64, cudaFuncAttributeMaxDynamicSharedMemorySize, KAN_SMEM);

    const int n4 = N_NODES * DFEAT / 4;
    const int scat_blocks = (NEDGES * 16 + 255) / 256;
    const int kan_blocks = (N_NODES + NTILE - 1) / NTILE;

    k_prep<<<(DFEAT * KTOT + 255) / 256, 256>>>(bw0, sw0, sc0, bw1, sw1, sc1, bwh, swh, sch);

    // layer 0: y0 = x + agg(x); h0 = KAN(y0), dual-stored into g_h and g_y2
    k_copy4<<<(n4 + 255) / 256, 256>>>((float4*)p_y, (const float4*)x, n4);
    k_scatter<<<scat_blocks, 256>>>(x, p_y, ei);
    k_kan64<<<kan_blocks, TPB, KAN_SMEM>>>(p_y, p_h, p_y2, p_W0);

    // layer 1: y1 = h0 + agg(h0) (y2 pre-seeded by dual store); h1 = KAN(y1)
    k_scatter<<<scat_blocks, 256>>>(p_h, p_y2, ei);
    k_kan64<<<kan_blocks, TPB, KAN_SMEM>>>(p_y2, p_y, (float*)nullptr, p_W1);

    // pool + head
    k_zero<<<(NGRAPHS * DFEAT + 255) / 256, 256>>>(p_pool, NGRAPHS * DFEAT);
    k_pool<<<(N_NODES * 16 + 255) / 256, 256>>>(p_y, batch);
    k_head<<<NGRAPHS, DFEAT>>>(out);
}

// round 10
// speedup vs baseline: 1.3507x; 1.1334x over previous
#include <cuda_runtime.h>
#include <cstdint>

#define N_NODES 100000
#define DFEAT   64
#define NCOEF   8
#define KTOT    576
#define NGRAPHS 512
#define NTARG   10
#define NEDGES  1200000

#define NTILE     128        // nodes per block in k_kan64
#define TPB       256
#define SF_STRIDE 68         // 272B rows: 16B aligned; warp-adjacent rows 16 banks apart
#define SW_STRIDE 68
#define BUF_FLOATS (64 * SW_STRIDE + NTILE * SF_STRIDE)       // 13056
#define KAN_SMEM  (2 * BUF_FLOATS * 4)                         // 104448 B

// ---------------- static device scratch (no allocation allowed) -------------
__device__ __align__(128) float g_y [N_NODES * DFEAT];
__device__ __align__(128) float g_h [N_NODES * DFEAT];
__device__ __align__(128) float g_y2[N_NODES * DFEAT];
__device__ __align__(128) float g_pool[NGRAPHS * DFEAT];
__device__ __align__(128) float g_W0[DFEAT * KTOT];
__device__ __align__(128) float g_W1[DFEAT * KTOT];
__device__ __align__(128) float g_Wh[NTARG * KTOT];

__device__ __forceinline__ float silu_f(float v) {
    return v / (1.0f + __expf(-v));
}

// closed-form uniform cubic B-spline: write the 8 basis values to dst[0..7].
// grid: t_j = (j-3)*0.4 - 1, j=0..11; support [-2.2, 2.2)
__device__ __forceinline__ void bspl8_store(float x, float* dst) {
    *(float4*)dst       = make_float4(0.f, 0.f, 0.f, 0.f);
    *(float4*)(dst + 4) = make_float4(0.f, 0.f, 0.f, 0.f);
    float p = (x + 2.2f) * 2.5f;
    if (p >= 0.0f && p < 11.0f) {
        int c = (int)p;            // cell index 0..10
        float u  = p - (float)c;
        float um = 1.0f - u;
        float u2 = u * u;
        float u3 = u2 * u;
        float w_s0 = u3 * (1.0f / 6.0f);                                        // B_c
        float w_s1 = (1.0f + 3.0f * u + 3.0f * u2 - 3.0f * u3) * (1.0f / 6.0f); // B_{c-1}
        float w_s2 = (4.0f - 6.0f * u2 + 3.0f * u3) * (1.0f / 6.0f);            // B_{c-2}
        float w_s3 = um * um * um * (1.0f / 6.0f);                              // B_{c-3}
        if (c     <= 7)               dst[c]     = w_s0;
        if (c - 1 >= 0 && c - 1 <= 7) dst[c - 1] = w_s1;
        if (c - 2 >= 0 && c - 2 <= 7) dst[c - 2] = w_s2;
        if (c - 3 >= 0)               dst[c - 3] = w_s3;
    }
}

__device__ __forceinline__ void bspl8_reg(float x, float b[8]) {
    float tmp[8];
    bspl8_store(x, tmp);
#pragma unroll
    for (int g = 0; g < 8; g++) b[g] = tmp[g];
}

// ---------------- weight prep: W_eff[o][k] ----------------------------------
__global__ void k_prep(const float* __restrict__ bw0, const float* __restrict__ sw0, const float* __restrict__ sc0,
                       const float* __restrict__ bw1, const float* __restrict__ sw1, const float* __restrict__ sc1,
                       const float* __restrict__ bwh, const float* __restrict__ swh, const float* __restrict__ sch) {
    int idx = blockIdx.x * blockDim.x + threadIdx.x;
    if (idx >= DFEAT * KTOT) return;
    int o = idx / KTOT, k = idx % KTOT;
    float v0, v1;
    if (k < DFEAT) {
        v0 = bw0[o * DFEAT + k];
        v1 = bw1[o * DFEAT + k];
    } else {
        int k2 = k - DFEAT;
        int i = k2 >> 3, g = k2 & 7;
        v0 = sw0[(o * DFEAT + i) * NCOEF + g] * sc0[o * DFEAT + i];
        v1 = sw1[(o * DFEAT + i) * NCOEF + g] * sc1[o * DFEAT + i];
    }
    g_W0[idx] = v0;
    g_W1[idx] = v1;
    if (o < NTARG) {
        float vh;
        if (k < DFEAT) {
            vh = bwh[o * DFEAT + k];
        } else {
            int k2 = k - DFEAT;
            int i = k2 >> 3, g = k2 & 7;
            vh = swh[(o * DFEAT + i) * NCOEF + g] * sch[o * DFEAT + i];
        }
        g_Wh[o * KTOT + k] = vh;
    }
}

// ---------------- utility kernels -------------------------------------------
__global__ void k_copy4(float4* __restrict__ dst, const float4* __restrict__ src, int n4) {
    int i = blockIdx.x * blockDim.x + threadIdx.x;
    if (i < n4) dst[i] = src[i];
}

__global__ void k_zero(float* __restrict__ dst, int n) {
    int i = blockIdx.x * blockDim.x + threadIdx.x;
    if (i < n) dst[i] = 0.0f;
}

// ---------------- edge scatter: dstbuf[dst] += feat[src] --------------------
__global__ void k_scatter(const float* __restrict__ feat, float* __restrict__ dstbuf,
                          const int* __restrict__ ei) {
    int idx = blockIdx.x * blockDim.x + threadIdx.x;
    if (idx >= NEDGES * 16) return;
    int e = idx >> 4;
    int c = idx & 15;
    int s = __ldg(&ei[e]);
    int d = __ldg(&ei[NEDGES + e]);
    float4 v = *(const float4*)(feat + (size_t)s * DFEAT + c * 4);
    float* p = dstbuf + (size_t)d * DFEAT + c * 4;
    asm volatile("red.global.add.v4.f32 [%0], {%1,%2,%3,%4};"
                 :: "l"(p), "f"(v.x), "f"(v.y), "f"(v.z), "f"(v.w)
                 : "memory");
}

// ---------------- graph pooling ---------------------------------------------
__global__ void k_pool(const float* __restrict__ hfeat, const int* __restrict__ batch) {
    int idx = blockIdx.x * blockDim.x + threadIdx.x;
    if (idx >= N_NODES * 16) return;
    int n = idx >> 4, c = idx & 15;
    int g = __ldg(&batch[n]);
    float4 v = *(const float4*)(hfeat + (size_t)n * DFEAT + c * 4);
    float* p = g_pool + g * DFEAT + c * 4;
    asm volatile("red.global.add.v4.f32 [%0], {%1,%2,%3,%4};"
                 :: "l"(p), "f"(v.x), "f"(v.y), "f"(v.z), "f"(v.w)
                 : "memory");
}

// ---------------- fused KAN 64->64 layer (R4 core + double buffer) ----------
// 128-node tile, 256 threads, thread tile 4 nodes x 8 outs (interleaved node
// map: thread (ng, og) covers nodes {ng, ng+32, ng+64, ng+96}).
// Two smem buffers: stage chunk kc+1 into the idle buffer while the GEMM
// consumes the current one; a single barrier per chunk orders
// stage-write(kc+1) / gemm-read(kc) against the next iteration.
// sF: stride 68 -> warp-consecutive ng rows land 16 banks apart, conflict-free.
// sW: rows permuted ((o&7)<<3 | o>>3), stride 68 -> 8 per-oo addresses cover
// offsets {0,16,...,112} mod 128, conflict-free.
__global__ __launch_bounds__(TPB, 2) void k_kan64(const float* __restrict__ yin,
                                                  float* __restrict__ hout,
                                                  float* __restrict__ hout2,
                                                  const float* __restrict__ W) {
    extern __shared__ float smem[];
    int tid = threadIdx.x;
    int nb = blockIdx.x * NTILE;
    int ng = tid >> 3;  // 0..31
    int og = tid & 7;   // 0..7 -> outs og*8 .. og*8+7

    float acc[4][8];
#pragma unroll
    for (int a = 0; a < 4; a++)
#pragma unroll
        for (int b = 0; b < 8; b++) acc[a][b] = 0.0f;

    // ---- stage chunk 0 into buffer 0 (W + silu features) ----
    {
        float* sW = smem;
        float* sF = smem + 64 * SW_STRIDE;
#pragma unroll
        for (int r = 0; r < 4; r++) {
            int idx = r * TPB + tid;         // 0..1023
            int o = idx >> 4, kq = idx & 15;
            float4 wv4 = *(const float4*)&W[o * KTOT + kq * 4];
            int pr = ((o & 7) << 3) | (o >> 3);
            *(float4*)&sW[pr * SW_STRIDE + kq * 4] = wv4;
        }
#pragma unroll
        for (int r = 0; r < 8; r++) {
            int idx = r * TPB + tid;         // 0..2047 float4 units
            int n = idx >> 4, kq = idx & 15;
            int gn = nb + n; if (gn >= N_NODES) gn = N_NODES - 1;
            float4 v = *(const float4*)&yin[(size_t)gn * DFEAT + kq * 4];
            float4 s;
            s.x = silu_f(v.x); s.y = silu_f(v.y);
            s.z = silu_f(v.z); s.w = silu_f(v.w);
            *(float4*)&sF[n * SF_STRIDE + kq * 4] = s;
        }
    }
    __syncthreads();

    for (int kc = 0; kc < 9; kc++) {
        int cur = kc & 1;
        float* sWc = smem + cur * BUF_FLOATS;
        float* sFc = sWc + 64 * SW_STRIDE;
        float* sWn = smem + (cur ^ 1) * BUF_FLOATS;
        float* sFn = sWn + 64 * SW_STRIDE;

        // ---- stage chunk kc+1 into the idle buffer (overlaps GEMM below) ----
        if (kc < 8) {
#pragma unroll
            for (int r = 0; r < 4; r++) {
                int idx = r * TPB + tid;     // 0..1023
                int o = idx >> 4, kq = idx & 15;
                float4 wv4 = *(const float4*)&W[o * KTOT + (kc + 1) * 64 + kq * 4];
                int pr = ((o & 7) << 3) | (o >> 3);
                *(float4*)&sWn[pr * SW_STRIDE + kq * 4] = wv4;
            }
#pragma unroll
            for (int r = 0; r < 4; r++) {
                int idx = r * TPB + tid;     // 0..1023 (n, ii)
                int n = idx >> 3, ii = idx & 7;
                int gn = nb + n; if (gn >= N_NODES) gn = N_NODES - 1;
                float v = yin[(size_t)gn * DFEAT + kc * 8 + ii];
                bspl8_store(v, &sFn[n * SF_STRIDE + ii * 8]);
            }
        }

        // ---- GEMM over the current 64-wide K chunk ----
#pragma unroll
        for (int k = 0; k < 64; k += 4) {
            float4 fv[4];
#pragma unroll
            for (int nn = 0; nn < 4; nn++)
                fv[nn] = *(const float4*)&sFc[(nn * 32 + ng) * SF_STRIDE + k];
#pragma unroll
            for (int oo = 0; oo < 8; oo++) {
                float4 wv = *(const float4*)&sWc[(oo * 8 + og) * SW_STRIDE + k];
#pragma unroll
                for (int nn = 0; nn < 4; nn++) {
                    acc[nn][oo] += fv[nn].x * wv.x + fv[nn].y * wv.y
                                 + fv[nn].z * wv.z + fv[nn].w * wv.w;
                }
            }
        }
        __syncthreads();
    }

    // store: thread covers nodes nn*32+ng, outputs og*8..og*8+7
#pragma unroll
    for (int nn = 0; nn < 4; nn++) {
        int gn = nb + nn * 32 + ng;
        if (gn < N_NODES) {
            float4 v0 = make_float4(acc[nn][0], acc[nn][1], acc[nn][2], acc[nn][3]);
            float4 v1 = make_float4(acc[nn][4], acc[nn][5], acc[nn][6], acc[nn][7]);
            size_t base = (size_t)gn * DFEAT + og * 8;
            *(float4*)(hout + base)     = v0;
            *(float4*)(hout + base + 4) = v1;
            if (hout2) {
                *(float4*)(hout2 + base)     = v0;
                *(float4*)(hout2 + base + 4) = v1;
            }
        }
    }
}

// ---------------- KAN head 64 -> 10 over pooled graphs ----------------------
__global__ void k_head(float* __restrict__ out) {
    __shared__ float sF[KTOT];
    int g = blockIdx.x;
    int t = threadIdx.x;  // 64 threads
    float v = g_pool[g * DFEAT + t];
    sF[t] = silu_f(v);
    float b[8];
    bspl8_reg(v, b);
#pragma unroll
    for (int gg = 0; gg < 8; gg++) sF[DFEAT + t * 8 + gg] = b[gg];
    __syncthreads();
    if (t < NTARG) {
        const float* w = g_Wh + t * KTOT;
        float acc = 0.0f;
#pragma unroll 8
        for (int k = 0; k < KTOT; k++) acc += sF[k] * w[k];
        out[g * NTARG + t] = acc;
    }
}

// ---------------- launch -----------------------------------------------------
extern "C" void kernel_launch(void* const* d_in, const int* in_sizes, int n_in,
                              void* d_out, int out_size) {
    const float* x      = (const float*)d_in[0];
    const int*   ei     = (const int*)d_in[1];
    const int*   batch  = (const int*)d_in[2];
    const float* bw0    = (const float*)d_in[3];
    const float* sw0    = (const float*)d_in[4];
    const float* sc0    = (const float*)d_in[5];
    const float* bw1    = (const float*)d_in[6];
    const float* sw1    = (const float*)d_in[7];
    const float* sc1    = (const float*)d_in[8];
    const float* bwh    = (const float*)d_in[9];
    const float* swh    = (const float*)d_in[10];
    const float* sch    = (const float*)d_in[11];
    float* out = (float*)d_out;

    float *p_y, *p_h, *p_y2, *p_pool, *p_W0, *p_W1;
    cudaGetSymbolAddress((void**)&p_y,    g_y);
    cudaGetSymbolAddress((void**)&p_h,    g_h);
    cudaGetSymbolAddress((void**)&p_y2,   g_y2);
    cudaGetSymbolAddress((void**)&p_pool, g_pool);
    cudaGetSymbolAddress((void**)&p_W0,   g_W0);
    cudaGetSymbolAddress((void**)&p_W1,   g_W1);

    cudaFuncSetAttribute(k_kan64, cudaFuncAttributeMaxDynamicSharedMemorySize, KAN_SMEM);

    const int n4 = N_NODES * DFEAT / 4;
    const int scat_blocks = (NEDGES * 16 + 255) / 256;
    const int kan_blocks = (N_NODES + NTILE - 1) / NTILE;

    k_prep<<<(DFEAT * KTOT + 255) / 256, 256>>>(bw0, sw0, sc0, bw1, sw1, sc1, bwh, swh, sch);

    // layer 0: y0 = x + agg(x); h0 = KAN(y0), dual-stored into g_h and g_y2
    k_copy4<<<(n4 + 255) / 256, 256>>>((float4*)p_y, (const float4*)x, n4);
    k_scatter<<<scat_blocks, 256>>>(x, p_y, ei);
    k_kan64<<<kan_blocks, TPB, KAN_SMEM>>>(p_y, p_h, p_y2, p_W0);

    // layer 1: y1 = h0 + agg(h0) (y2 pre-seeded by dual store); h1 = KAN(y1)
    k_scatter<<<scat_blocks, 256>>>(p_h, p_y2, ei);
    k_kan64<<<kan_blocks, TPB, KAN_SMEM>>>(p_y2, p_y, (float*)nullptr, p_W1);

    // pool + head
    k_zero<<<(NGRAPHS * DFEAT + 255) / 256, 256>>>(p_pool, NGRAPHS * DFEAT);
    k_pool<<<(N_NODES * 16 + 255) / 256, 256>>>(p_y, batch);
    k_head<<<NGRAPHS, DFEAT>>>(out);
}